// round 14
// baseline (speedup 1.0000x reference)
#include <cuda_runtime.h>
#include <cuda_bf16.h>
#include <cstdint>

#define B    8
#define T    512
#define U1   65
#define V    128
#define ENC  512
#define PRED 256
#define JOIN 512
#define NTOK 64

// ---- k_joint v4 smem layout (1 barrier/chunk, warp-own build) ----
#define CHUNK32_B  20480                    // one k32 chunk: hi(10240)+lo(10240)
#define J_A        0                        // 2 bufs x 20480
#define J_B        40960                    // 2 bufs x 20480
#define J_EP       81920                    // 2 slots x 2048 (16 rows x 32 f)
#define J_PP       86016                    // 8 rows x 520 floats = 16640
#define J_BIAS     102656                   // 512
#define SMEM_J4    103168

// ---- k_all enc-role smem layout (2-deep, fits 2 blocks/SM) ----
#define E_RAW      0                        // 2 slots x 16896 (32 x 132 floats)
#define E_ENC      33792                    // 2 slots x 8192  (64 x 32 floats)
#define E_A        50176                    // 2 bufs  x 10240 (hi 5120 + lo 5120)
#define E_B        70656                    // 2 bufs  x 20480 (hi 10240 + lo 10240)
#define SMEM_ALL3  111616

// ---------------- device scratch (no allocations allowed) ----------------
__device__ __align__(16) float g_pp[B * U1 * JOIN];   // pred_proj + bj1
__device__ __align__(16) float g_ep[B * T * JOIN];    // enc_proj
__device__ __align__(16) unsigned char g_bt2[16 * CHUNK32_B];  // Wj2 images (k32 layout)

// ---------------- helpers ----------------
__device__ __forceinline__ uint32_t smem_u32(const void* p) {
    uint32_t a;
    asm("{ .reg .u64 t; cvta.to.shared.u64 t, %1; cvt.u32.u64 %0, t; }" : "=r"(a) : "l"(p));
    return a;
}
__device__ __forceinline__ void ldsm4(uint32_t* r, uint32_t addr) {
    asm volatile("ldmatrix.sync.aligned.m8n8.x4.shared.b16 {%0,%1,%2,%3}, [%4];"
        : "=r"(r[0]), "=r"(r[1]), "=r"(r[2]), "=r"(r[3]) : "r"(addr));
}
__device__ __forceinline__ void mma_bf16(float* c, const uint32_t* a, const uint32_t* b) {
    asm volatile("mma.sync.aligned.m16n8k16.row.col.f32.bf16.bf16.f32 "
        "{%0,%1,%2,%3}, {%4,%5,%6,%7}, {%8,%9}, {%0,%1,%2,%3};"
        : "+f"(c[0]), "+f"(c[1]), "+f"(c[2]), "+f"(c[3])
        : "r"(a[0]), "r"(a[1]), "r"(a[2]), "r"(a[3]), "r"(b[0]), "r"(b[1]));
}
#define CP_ASYNC16(dst, src) \
    asm volatile("cp.async.cg.shared.global [%0], [%1], 16;" :: "r"(dst), "l"(src))
#define CP_COMMIT() asm volatile("cp.async.commit_group;" ::: "memory")
#define CP_WAIT0()  asm volatile("cp.async.wait_group 0;" ::: "memory")

// ======================================================================
// k_all (R12 known-good, byte-identical): grid = 385.
// ======================================================================
__global__ __launch_bounds__(256, 2)
void k_all(const float* __restrict__ enc, const int* __restrict__ es_arr,
           const void* __restrict__ targets_raw,
           const float* __restrict__ emb,
           const float* __restrict__ W1, const float* __restrict__ b1,
           const float* __restrict__ W2, const float* __restrict__ b2,
           const float* __restrict__ Wj1, const float* __restrict__ bj1,
           const float* __restrict__ Wj2) {
    extern __shared__ char sm[];
    int bx = blockIdx.x;
    int tid = threadIdx.x;

    if (bx < 65) {
        float* s_e = (float*)sm;                 // [8][256]
        float* s_p = s_e + 8 * 256;
        float* s_q = s_p + 8 * 256;
        __shared__ int s_is64;
        int r0 = bx * 8;

        if (tid == 0) {
            const int* w = (const int*)targets_raw;
            int z = 0;
            #pragma unroll
            for (int i = 1; i < 64; i += 2) z |= w[i];
            s_is64 = (z == 0) ? 1 : 0;
        }
        __syncthreads();
        int is64 = s_is64;

        #pragma unroll
        for (int i = 0; i < 8; i++) {
            int idx = i * 256 + tid;
            int rr = idx >> 8, rest = idx & 255;
            int half = rest >> 7, ei = rest & 127;
            int row = r0 + rr;
            int b = row / U1, u = row % U1;
            int tix = u - 1 - half;
            int tok = V - 1;
            if (tix >= 0) {
                if (is64) tok = (int)((const long long*)targets_raw)[b * NTOK + tix];
                else      tok = ((const int*)targets_raw)[b * NTOK + tix];
            }
            s_e[rr * 256 + half * 128 + ei] = emb[tok * 128 + ei];
        }
        __syncthreads();

        {
            float acc[8];
            float bb = b1[tid];
            #pragma unroll
            for (int r = 0; r < 8; r++) acc[r] = bb;
            for (int k0 = 0; k0 < 256; k0 += 16) {
                float w[16];
                #pragma unroll
                for (int i = 0; i < 16; i++) w[i] = W1[(k0 + i) * PRED + tid];
                #pragma unroll
                for (int i = 0; i < 16; i++)
                    #pragma unroll
                    for (int r = 0; r < 8; r++)
                        acc[r] = fmaf(s_e[r * 256 + k0 + i], w[i], acc[r]);
            }
            #pragma unroll
            for (int r = 0; r < 8; r++) s_p[r * 256 + tid] = fmaxf(acc[r], 0.f);
        }
        __syncthreads();

        {
            float acc[8];
            float bb = b2[tid];
            #pragma unroll
            for (int r = 0; r < 8; r++) acc[r] = bb;
            for (int k0 = 0; k0 < 256; k0 += 16) {
                float w[16];
                #pragma unroll
                for (int i = 0; i < 16; i++) w[i] = W2[(k0 + i) * PRED + tid];
                #pragma unroll
                for (int i = 0; i < 16; i++)
                    #pragma unroll
                    for (int r = 0; r < 8; r++)
                        acc[r] = fmaf(s_p[r * 256 + k0 + i], w[i], acc[r]);
            }
            #pragma unroll
            for (int r = 0; r < 8; r++) s_q[r * 256 + tid] = fmaxf(acc[r], 0.f);
        }
        __syncthreads();

        {
            float acc0[8], acc1[8];
            float bb0 = bj1[tid], bb1 = bj1[tid + 256];
            #pragma unroll
            for (int r = 0; r < 8; r++) { acc0[r] = bb0; acc1[r] = bb1; }
            const float* Wp = Wj1 + (size_t)ENC * JOIN;
            for (int k0 = 0; k0 < 256; k0 += 8) {
                float w0[8], w1[8];
                #pragma unroll
                for (int i = 0; i < 8; i++) {
                    w0[i] = Wp[(k0 + i) * JOIN + tid];
                    w1[i] = Wp[(k0 + i) * JOIN + tid + 256];
                }
                #pragma unroll
                for (int i = 0; i < 8; i++) {
                    #pragma unroll
                    for (int r = 0; r < 8; r++) {
                        float q = s_q[r * 256 + k0 + i];
                        acc0[r] = fmaf(q, w0[i], acc0[r]);
                        acc1[r] = fmaf(q, w1[i], acc1[r]);
                    }
                }
            }
            #pragma unroll
            for (int r = 0; r < 8; r++) {
                g_pp[(size_t)(r0 + r) * JOIN + tid]       = acc0[r];
                g_pp[(size_t)(r0 + r) * JOIN + tid + 256] = acc1[r];
            }
        }
        return;
    }

    if (bx < 129) {
        int base_i = (bx - 65) * 1024;
        #pragma unroll
        for (int i = 0; i < 4; i++) {
            int idx = base_i + i * 256 + tid;       // < 65536
            int k = idx >> 7, n = idx & 127;
            float w = Wj2[idx];
            __nv_bfloat16 hi = __float2bfloat16(w);
            __nv_bfloat16 lo = __float2bfloat16(w - __bfloat162float(hi));
            size_t dst = (size_t)(k >> 5) * CHUNK32_B + (size_t)n * 80 + (k & 31) * 2;
            *(__nv_bfloat16*)(g_bt2 + dst)         = hi;
            *(__nv_bfloat16*)(g_bt2 + dst + 10240) = lo;
        }
        return;
    }

    // enc role: M=64 x N=128 x K=512, 2-deep pipeline
    {
        int ebx = bx - 129;
        int b = ebx >> 5, tt = (ebx >> 2) & 7, nt = ebx & 3;
        int t0 = tt * 64;
        if (t0 >= es_arr[b]) return;
        int lane = tid & 31, wid = tid >> 5;
        int wm = wid & 1, wn = wid >> 1;     // 2m x 4n warps
        uint32_t sb = smem_u32(sm);

#define E_STAGE(c_) do {                                                            \
        int sl_ = (c_) & 1;                                                         \
        uint32_t rdst_ = sb + E_RAW + sl_ * 16896;                                  \
        _Pragma("unroll")                                                           \
        for (int i_ = 0; i_ < 4; i_++) {                                            \
            int idx_ = i_ * 256 + tid;                                              \
            int kk_ = idx_ >> 5, n4_ = idx_ & 31;                                   \
            CP_ASYNC16(rdst_ + kk_ * 528 + n4_ * 16,                                \
                &Wj1[(size_t)((c_) * 32 + kk_) * JOIN + nt * 128 + n4_ * 4]);       \
        }                                                                           \
        uint32_t edst_ = sb + E_ENC + sl_ * 8192;                                   \
        _Pragma("unroll")                                                           \
        for (int i_ = 0; i_ < 2; i_++) {                                            \
            int idx_ = i_ * 256 + tid;                                              \
            int row_ = idx_ >> 3, c4_ = idx_ & 7;                                   \
            CP_ASYNC16(edst_ + row_ * 128 + c4_ * 16,                               \
                &enc[(size_t)(b * T + t0 + row_) * ENC + (c_) * 32 + c4_ * 4]);     \
        }                                                                           \
    } while (0)

#define E_BUILD(c_) do {                                                            \
        int sl_ = (c_) & 1;                                                         \
        const float* s_raw_ = (const float*)(sm + E_RAW + sl_ * 16896);             \
        const float* s_enc_ = (const float*)(sm + E_ENC + sl_ * 8192);              \
        uint32_t ab_ = (uint32_t)E_A + sl_ * 10240;                                 \
        uint32_t bb_ = (uint32_t)E_B + sl_ * 20480;                                 \
        _Pragma("unroll")                                                           \
        for (int i_ = 0; i_ < 8; i_++) {       /* B: 2048 units */                  \
            int idx_ = i_ * 256 + tid;                                              \
            int n_ = idx_ & 127, kp_ = idx_ >> 7;                                   \
            float f0_ = s_raw_[(2 * kp_) * 132 + n_];                               \
            float f1_ = s_raw_[(2 * kp_ + 1) * 132 + n_];                           \
            __nv_bfloat162 hp_ = __floats2bfloat162_rn(f0_, f1_);                   \
            float2 hf_ = __bfloat1622float2(hp_);                                   \
            __nv_bfloat162 lp_ = __floats2bfloat162_rn(f0_ - hf_.x, f1_ - hf_.y);   \
            uint32_t off_ = bb_ + (uint32_t)n_ * 80 + kp_ * 4;                      \
            *(__nv_bfloat162*)(sm + off_) = hp_;                                    \
            *(__nv_bfloat162*)(sm + off_ + 10240) = lp_;                            \
        }                                                                           \
        _Pragma("unroll")                                                           \
        for (int i_ = 0; i_ < 4; i_++) {       /* A: 1024 units */                  \
            int idx_ = i_ * 256 + tid;                                              \
            int row_ = idx_ >> 4, kp_ = idx_ & 15;                                  \
            float2 e_ = *(const float2*)&s_enc_[row_ * 32 + 2 * kp_];               \
            __nv_bfloat162 hp_ = __floats2bfloat162_rn(e_.x, e_.y);                 \
            float2 hf_ = __bfloat1622float2(hp_);                                   \
            __nv_bfloat162 lp_ = __floats2bfloat162_rn(e_.x - hf_.x, e_.y - hf_.y); \
            uint32_t off_ = ab_ + (uint32_t)row_ * 80 + kp_ * 4;                    \
            *(__nv_bfloat162*)(sm + off_) = hp_;                                    \
            *(__nv_bfloat162*)(sm + off_ + 5120) = lp_;                             \
        }                                                                           \
    } while (0)

        float acc[2][4][4];
        #pragma unroll
        for (int i = 0; i < 2; i++)
            #pragma unroll
            for (int j = 0; j < 4; j++)
                #pragma unroll
                for (int q = 0; q < 4; q++) acc[i][j][q] = 0.f;

        uint32_t a_base = sb + E_A + (uint32_t)(wm * 32 + (lane & 15)) * 80
                        + ((lane >> 4) << 4);
        uint32_t b_base = sb + E_B + (uint32_t)(wn * 32 + (lane & 7) + ((lane >> 4) << 3)) * 80
                        + (((lane >> 3) & 1) << 4);

        E_STAGE(0); CP_COMMIT();
        CP_WAIT0();
        __syncthreads();
        E_BUILD(0);

        for (int c = 0; c < 16; c++) {
            __syncthreads();
            if (c + 1 < 16) { E_STAGE(c + 1); CP_COMMIT(); }
            {
                uint32_t ab = a_base + (c & 1) * 10240;
                uint32_t bb = b_base + (c & 1) * 20480;
                #pragma unroll
                for (int s = 0; s < 2; s++) {
                    uint32_t ah[2][4], al[2][4];
                    #pragma unroll
                    for (int mi = 0; mi < 2; mi++) {
                        ldsm4(ah[mi], ab + mi * 1280 + s * 32);
                        ldsm4(al[mi], ab + mi * 1280 + s * 32 + 5120);
                    }
                    #pragma unroll
                    for (int j2 = 0; j2 < 2; j2++) {
                        uint32_t bh[4], bl[4];
                        ldsm4(bh, bb + j2 * 1280 + s * 32);
                        ldsm4(bl, bb + j2 * 1280 + s * 32 + 10240);
                        #pragma unroll
                        for (int mi = 0; mi < 2; mi++)
                            #pragma unroll
                            for (int jj = 0; jj < 2; jj++) {
                                int nj = j2 * 2 + jj;
                                mma_bf16(acc[mi][nj], ah[mi], &bh[jj * 2]);
                                mma_bf16(acc[mi][nj], ah[mi], &bl[jj * 2]);
                                mma_bf16(acc[mi][nj], al[mi], &bh[jj * 2]);
                            }
                    }
                }
            }
            if (c + 1 < 16) {
                CP_WAIT0();
                __syncthreads();
                E_BUILD(c + 1);
            }
        }
#undef E_STAGE
#undef E_BUILD

        int gid = lane >> 2, tig = lane & 3;
        #pragma unroll
        for (int mi = 0; mi < 2; mi++)
            #pragma unroll
            for (int nj = 0; nj < 4; nj++) {
                int col = nt * 128 + wn * 32 + nj * 8 + tig * 2;
                #pragma unroll
                for (int hh = 0; hh < 2; hh++) {
                    int row = wm * 32 + mi * 16 + gid + hh * 8;
                    int t = t0 + row;
                    *(float2*)&g_ep[((size_t)(b * T + t)) * JOIN + col] =
                        make_float2(acc[mi][nj][hh * 2], acc[mi][nj][hh * 2 + 1]);
                }
            }
    }
}

// ======================================================================
// k_joint v4 (fixed prologue): M=128 (16t x 8u) x N=128, 256 threads,
// 2 blocks/SM. ONE barrier per chunk; warp-own ep staging + A-build;
// pp hoisted to prologue; B 2-deep. grid = 2304.
// ======================================================================
__global__ __launch_bounds__(256, 2)
void k_joint(const int* __restrict__ es_arr, const int* __restrict__ ts_arr,
             const float* __restrict__ bj2, float* __restrict__ out) {
    extern __shared__ char sm[];
    int bx = blockIdx.x;
    int b = bx / 288, rem = bx % 288;
    int t0 = (rem / 9) * 16, u0 = (rem % 9) * 8;
    int es = es_arr[b], ts = ts_arr[b];
    int tid = threadIdx.x;
    bool live = (t0 < es) && (u0 <= ts);

    if (!live) {
        float4 z = make_float4(0.f, 0.f, 0.f, 0.f);
        #pragma unroll
        for (int i = 0; i < 16; i++) {
            int f4 = i * 256 + tid;
            int row = f4 >> 5, c4 = f4 & 31;
            int t = t0 + (row >> 3), u = u0 + (row & 7);
            if (u < U1)
                *(float4*)(out + (((size_t)(b * T + t) * U1 + u) << 7) + c4 * 4) = z;
        }
        return;
    }

    int lane = tid & 31, wid = tid >> 5;
    int wm = wid & 3, wn = wid >> 2;
    uint32_t sb = smem_u32(sm);
    float* s_bias = (float*)(sm + J_BIAS);
    if (tid < 128) s_bias[tid] = bj2[tid];

    // ---- prologue: stage whole pp tile (8 rows x 512 = 1024 float4 units) ----
    #pragma unroll
    for (int i = 0; i < 4; i++) {
        int idx = i * 256 + tid;            // 0..1023
        int ui = idx >> 7, f4 = idx & 127;
        int uu = u0 + ui; if (uu > 64) uu = 64;
        CP_ASYNC16(sb + J_PP + ui * 2080 + f4 * 16,
                   &g_pp[((size_t)(b * U1 + uu)) * JOIN + f4 * 4]);
    }

    // staging macros
#define STAGE_B(c_) do {                                                            \
        const char* bsrc_ = (const char*)g_bt2 + (size_t)(c_) * CHUNK32_B;          \
        uint32_t bdst_ = sb + J_B + ((c_) & 1) * CHUNK32_B;                         \
        _Pragma("unroll")                                                           \
        for (int i_ = 0; i_ < 5; i_++) {                                            \
            int idx_ = i_ * 256 + tid;                                              \
            CP_ASYNC16(bdst_ + idx_ * 16, bsrc_ + idx_ * 16);                       \
        }                                                                           \
    } while (0)

    // per-warp ep staging: warp wid stages ti rows {2*wid, 2*wid+1}
#define STAGE_EP(c_) do {                                                           \
        if (lane < 16) {                                                            \
            int tl_ = lane >> 3, c4_ = lane & 7;                                    \
            int ti_ = wid * 2 + tl_;                                                \
            CP_ASYNC16(sb + J_EP + ((c_) & 1) * 2048 + ti_ * 128 + c4_ * 16,        \
                &g_ep[((size_t)(b * T + t0 + ti_)) * JOIN + (c_) * 32 + c4_ * 4]);  \
        }                                                                           \
    } while (0)

    // per-warp A build: warp wid builds rows 16*wid .. 16*wid+15
#define BUILD_A(c_) do {                                                            \
        uint32_t ab_ = (uint32_t)J_A + ((c_) & 1) * CHUNK32_B;                      \
        const float* s_ep_ = (const float*)(sm + J_EP + ((c_) & 1) * 2048);         \
        const float* s_pp_ = (const float*)(sm + J_PP);                             \
        _Pragma("unroll")                                                           \
        for (int i_ = 0; i_ < 8; i_++) {                                            \
            int p_ = i_ * 32 + lane;                                                \
            int rl_ = p_ >> 4, kp_ = p_ & 15;                                       \
            int row_ = wid * 16 + rl_;                                              \
            int ti_ = row_ >> 3, ui_ = row_ & 7;                                    \
            float2 e_ = *(const float2*)&s_ep_[ti_ * 32 + 2 * kp_];                 \
            float2 q_ = *(const float2*)&s_pp_[ui_ * 520 + (c_) * 32 + 2 * kp_];    \
            float h0_ = fmaxf(e_.x + q_.x, 0.f), h1_ = fmaxf(e_.y + q_.y, 0.f);     \
            __nv_bfloat162 hp_ = __floats2bfloat162_rn(h0_, h1_);                   \
            float2 hf_ = __bfloat1622float2(hp_);                                   \
            __nv_bfloat162 lp_ = __floats2bfloat162_rn(h0_ - hf_.x, h1_ - hf_.y);   \
            uint32_t off_ = ab_ + (uint32_t)row_ * 80 + kp_ * 4;                    \
            *(__nv_bfloat162*)(sm + off_) = hp_;                                    \
            *(__nv_bfloat162*)(sm + off_ + 10240) = lp_;                            \
        }                                                                           \
    } while (0)

    float acc[2][8][4];
    #pragma unroll
    for (int i = 0; i < 2; i++)
        #pragma unroll
        for (int j = 0; j < 8; j++)
            #pragma unroll
            for (int q = 0; q < 4; q++) acc[i][j][q] = 0.f;

    uint32_t a_base = sb + J_A + (uint32_t)(wm * 32 + (lane & 15)) * 80 + ((lane >> 4) << 4);
    uint32_t b_base = sb + J_B + (uint32_t)(wn * 64 + (lane & 7) + ((lane >> 4) << 3)) * 80
                    + (((lane >> 3) & 1) << 4);

    // prologue: stage chunk 0 (pp already queued in the same group)
    STAGE_B(0);
    STAGE_EP(0);
    CP_COMMIT();
    CP_WAIT0();
    __syncthreads();          // pp + B(0) + ep(0) visible block-wide
    BUILD_A(0);

    for (int c = 0; c < 16; c++) {
        __syncthreads();      // A(c) built by all warps; B(c) staged & visible
        if (c + 1 < 16) { STAGE_B(c + 1); STAGE_EP(c + 1); CP_COMMIT(); }
        // ---- MMA(c) ----
        {
            uint32_t ab = a_base + (c & 1) * CHUNK32_B;
            uint32_t bb = b_base + (c & 1) * CHUNK32_B;
            #pragma unroll
            for (int s = 0; s < 2; s++) {
                uint32_t ah[2][4], al[2][4];
                #pragma unroll
                for (int mi = 0; mi < 2; mi++) {
                    ldsm4(ah[mi], ab + mi * 1280 + s * 32);
                    ldsm4(al[mi], ab + mi * 1280 + s * 32 + 10240);
                }
                #pragma unroll
                for (int j2 = 0; j2 < 4; j2++) {
                    uint32_t bh[4], bl[4];
                    ldsm4(bh, bb + j2 * 1280 + s * 32);
                    ldsm4(bl, bb + j2 * 1280 + s * 32 + 10240);
                    #pragma unroll
                    for (int mi = 0; mi < 2; mi++)
                        #pragma unroll
                        for (int jj = 0; jj < 2; jj++) {
                            int nj = j2 * 2 + jj;
                            mma_bf16(acc[mi][nj], ah[mi], &bh[jj * 2]);
                            mma_bf16(acc[mi][nj], ah[mi], &bl[jj * 2]);
                            mma_bf16(acc[mi][nj], al[mi], &bh[jj * 2]);
                        }
                }
            }
        }
        // ---- build A(c+1): warp-private, no block barrier needed ----
        if (c + 1 < 16) {
            CP_WAIT0();       // own B+ep copies done
            __syncwarp();     // ep staged by lanes<16 visible warp-wide
            BUILD_A(c + 1);
        }
    }
#undef STAGE_B
#undef STAGE_EP
#undef BUILD_A

    // epilogue: bias + mask + store
    int gid = lane >> 2, tig = lane & 3;
    #pragma unroll
    for (int mi = 0; mi < 2; mi++)
        #pragma unroll
        for (int nj = 0; nj < 8; nj++) {
            int col = wn * 64 + nj * 8 + tig * 2;
            float b0f = s_bias[col], b1f = s_bias[col + 1];
            #pragma unroll
            for (int hh = 0; hh < 2; hh++) {
                int row = wm * 32 + mi * 16 + gid + hh * 8;
                int t = t0 + (row >> 3), u = u0 + (row & 7);
                if (u >= U1) continue;
                bool valid = (t < es) && (u <= ts);
                float v0 = valid ? acc[mi][nj][hh * 2]     + b0f : 0.f;
                float v1 = valid ? acc[mi][nj][hh * 2 + 1] + b1f : 0.f;
                *(float2*)(out + (((size_t)(b * T + t) * U1 + u) << 7) + col) =
                    make_float2(v0, v1);
            }
        }
}

extern "C" void kernel_launch(void* const* d_in, const int* in_sizes, int n_in,
                              void* d_out, int out_size) {
    const float* enc  = (const float*)d_in[0];
    const int*   es   = (const int*)  d_in[1];
    const void*  tgt  =               d_in[2];   // int64 or int32, auto-detected
    const int*   ts   = (const int*)  d_in[3];
    const float* emb  = (const float*)d_in[4];
    const float* W1   = (const float*)d_in[5];
    const float* b1   = (const float*)d_in[6];
    const float* W2   = (const float*)d_in[7];
    const float* b2   = (const float*)d_in[8];
    const float* Wj1  = (const float*)d_in[9];
    const float* bj1  = (const float*)d_in[10];
    const float* Wj2  = (const float*)d_in[11];
    const float* bj2  = (const float*)d_in[12];
    float* out = (float*)d_out;

    static bool attr_done = false;
    if (!attr_done) {
        cudaFuncSetAttribute(k_all,   cudaFuncAttributeMaxDynamicSharedMemorySize, SMEM_ALL3);
        cudaFuncSetAttribute(k_joint, cudaFuncAttributeMaxDynamicSharedMemorySize, SMEM_J4);
        attr_done = true;
    }

    k_all  <<<385, 256, SMEM_ALL3>>>(enc, es, tgt, emb, W1, b1, W2, b2, Wj1, bj1, Wj2);
    k_joint<<<2304, 256, SMEM_J4>>>(es, ts, bj2, out);
}

// round 15
// speedup vs baseline: 1.1220x; 1.1220x over previous
#include <cuda_runtime.h>
#include <cuda_bf16.h>
#include <cuda_fp16.h>
#include <cstdint>

#define B    8
#define T    512
#define U1   65
#define V    128
#define ENC  512
#define PRED 256
#define JOIN 512
#define NTOK 64

// ---- k_joint v5 smem layout (fp16 A, fp16-split-2 B) ----
#define CHUNK32_B  20480                    // one k32 B chunk: hi(10240)+lo(10240)
#define A_BUF_B    10240                    // one k32 A buf: hi only
#define J_A        0                        // 2 bufs x 10240
#define J_B        20480                    // 2 bufs x 20480
#define J_EP       61440                    // 2 slots x 2048 (16 rows x 32 f)
#define J_PP       65536                    // 8 rows x 520 floats = 16640
#define J_BIAS     82176                    // 512
#define SMEM_J5    82688

// ---- k_all enc-role smem layout (2-deep, fits 2 blocks/SM) ----
#define E_RAW      0                        // 2 slots x 16896 (32 x 132 floats)
#define E_ENC      33792                    // 2 slots x 8192  (64 x 32 floats)
#define E_A        50176                    // 2 bufs  x 10240 (hi 5120 + lo 5120)
#define E_B        70656                    // 2 bufs  x 20480 (hi 10240 + lo 10240)
#define SMEM_ALL3  111616

// ---------------- device scratch (no allocations allowed) ----------------
__device__ __align__(16) float g_pp[B * U1 * JOIN];   // pred_proj + bj1
__device__ __align__(16) float g_ep[B * T * JOIN];    // enc_proj
__device__ __align__(16) unsigned char g_bt2[16 * CHUNK32_B];  // Wj2 fp16 hi/lo images

// ---------------- helpers ----------------
__device__ __forceinline__ uint32_t smem_u32(const void* p) {
    uint32_t a;
    asm("{ .reg .u64 t; cvta.to.shared.u64 t, %1; cvt.u32.u64 %0, t; }" : "=r"(a) : "l"(p));
    return a;
}
__device__ __forceinline__ void ldsm4(uint32_t* r, uint32_t addr) {
    asm volatile("ldmatrix.sync.aligned.m8n8.x4.shared.b16 {%0,%1,%2,%3}, [%4];"
        : "=r"(r[0]), "=r"(r[1]), "=r"(r[2]), "=r"(r[3]) : "r"(addr));
}
__device__ __forceinline__ void mma_bf16(float* c, const uint32_t* a, const uint32_t* b) {
    asm volatile("mma.sync.aligned.m16n8k16.row.col.f32.bf16.bf16.f32 "
        "{%0,%1,%2,%3}, {%4,%5,%6,%7}, {%8,%9}, {%0,%1,%2,%3};"
        : "+f"(c[0]), "+f"(c[1]), "+f"(c[2]), "+f"(c[3])
        : "r"(a[0]), "r"(a[1]), "r"(a[2]), "r"(a[3]), "r"(b[0]), "r"(b[1]));
}
__device__ __forceinline__ void mma_f16(float* c, const uint32_t* a, const uint32_t* b) {
    asm volatile("mma.sync.aligned.m16n8k16.row.col.f32.f16.f16.f32 "
        "{%0,%1,%2,%3}, {%4,%5,%6,%7}, {%8,%9}, {%0,%1,%2,%3};"
        : "+f"(c[0]), "+f"(c[1]), "+f"(c[2]), "+f"(c[3])
        : "r"(a[0]), "r"(a[1]), "r"(a[2]), "r"(a[3]), "r"(b[0]), "r"(b[1]));
}
#define CP_ASYNC16(dst, src) \
    asm volatile("cp.async.cg.shared.global [%0], [%1], 16;" :: "r"(dst), "l"(src))
#define CP_COMMIT() asm volatile("cp.async.commit_group;" ::: "memory")
#define CP_WAIT0()  asm volatile("cp.async.wait_group 0;" ::: "memory")

// ======================================================================
// k_all: grid = 385. Same as known-good R12 EXCEPT prep role emits
// fp16 hi/lo Wj2 images (was bf16).
// ======================================================================
__global__ __launch_bounds__(256, 2)
void k_all(const float* __restrict__ enc, const int* __restrict__ es_arr,
           const void* __restrict__ targets_raw,
           const float* __restrict__ emb,
           const float* __restrict__ W1, const float* __restrict__ b1,
           const float* __restrict__ W2, const float* __restrict__ b2,
           const float* __restrict__ Wj1, const float* __restrict__ bj1,
           const float* __restrict__ Wj2) {
    extern __shared__ char sm[];
    int bx = blockIdx.x;
    int tid = threadIdx.x;

    if (bx < 65) {
        float* s_e = (float*)sm;                 // [8][256]
        float* s_p = s_e + 8 * 256;
        float* s_q = s_p + 8 * 256;
        __shared__ int s_is64;
        int r0 = bx * 8;

        if (tid == 0) {
            const int* w = (const int*)targets_raw;
            int z = 0;
            #pragma unroll
            for (int i = 1; i < 64; i += 2) z |= w[i];
            s_is64 = (z == 0) ? 1 : 0;
        }
        __syncthreads();
        int is64 = s_is64;

        #pragma unroll
        for (int i = 0; i < 8; i++) {
            int idx = i * 256 + tid;
            int rr = idx >> 8, rest = idx & 255;
            int half = rest >> 7, ei = rest & 127;
            int row = r0 + rr;
            int b = row / U1, u = row % U1;
            int tix = u - 1 - half;
            int tok = V - 1;
            if (tix >= 0) {
                if (is64) tok = (int)((const long long*)targets_raw)[b * NTOK + tix];
                else      tok = ((const int*)targets_raw)[b * NTOK + tix];
            }
            s_e[rr * 256 + half * 128 + ei] = emb[tok * 128 + ei];
        }
        __syncthreads();

        {
            float acc[8];
            float bb = b1[tid];
            #pragma unroll
            for (int r = 0; r < 8; r++) acc[r] = bb;
            for (int k0 = 0; k0 < 256; k0 += 16) {
                float w[16];
                #pragma unroll
                for (int i = 0; i < 16; i++) w[i] = W1[(k0 + i) * PRED + tid];
                #pragma unroll
                for (int i = 0; i < 16; i++)
                    #pragma unroll
                    for (int r = 0; r < 8; r++)
                        acc[r] = fmaf(s_e[r * 256 + k0 + i], w[i], acc[r]);
            }
            #pragma unroll
            for (int r = 0; r < 8; r++) s_p[r * 256 + tid] = fmaxf(acc[r], 0.f);
        }
        __syncthreads();

        {
            float acc[8];
            float bb = b2[tid];
            #pragma unroll
            for (int r = 0; r < 8; r++) acc[r] = bb;
            for (int k0 = 0; k0 < 256; k0 += 16) {
                float w[16];
                #pragma unroll
                for (int i = 0; i < 16; i++) w[i] = W2[(k0 + i) * PRED + tid];
                #pragma unroll
                for (int i = 0; i < 16; i++)
                    #pragma unroll
                    for (int r = 0; r < 8; r++)
                        acc[r] = fmaf(s_p[r * 256 + k0 + i], w[i], acc[r]);
            }
            #pragma unroll
            for (int r = 0; r < 8; r++) s_q[r * 256 + tid] = fmaxf(acc[r], 0.f);
        }
        __syncthreads();

        {
            float acc0[8], acc1[8];
            float bb0 = bj1[tid], bb1 = bj1[tid + 256];
            #pragma unroll
            for (int r = 0; r < 8; r++) { acc0[r] = bb0; acc1[r] = bb1; }
            const float* Wp = Wj1 + (size_t)ENC * JOIN;
            for (int k0 = 0; k0 < 256; k0 += 8) {
                float w0[8], w1[8];
                #pragma unroll
                for (int i = 0; i < 8; i++) {
                    w0[i] = Wp[(k0 + i) * JOIN + tid];
                    w1[i] = Wp[(k0 + i) * JOIN + tid + 256];
                }
                #pragma unroll
                for (int i = 0; i < 8; i++) {
                    #pragma unroll
                    for (int r = 0; r < 8; r++) {
                        float q = s_q[r * 256 + k0 + i];
                        acc0[r] = fmaf(q, w0[i], acc0[r]);
                        acc1[r] = fmaf(q, w1[i], acc1[r]);
                    }
                }
            }
            #pragma unroll
            for (int r = 0; r < 8; r++) {
                g_pp[(size_t)(r0 + r) * JOIN + tid]       = acc0[r];
                g_pp[(size_t)(r0 + r) * JOIN + tid + 256] = acc1[r];
            }
        }
        return;
    }

    if (bx < 129) {
        // prep role: Wj2 -> fp16 hi/lo images, k32 chunks, 80B row stride
        int base_i = (bx - 65) * 1024;
        #pragma unroll
        for (int i = 0; i < 4; i++) {
            int idx = base_i + i * 256 + tid;       // < 65536
            int k = idx >> 7, n = idx & 127;
            float w = Wj2[idx];
            __half hi = __float2half_rn(w);
            __half lo = __float2half_rn(w - __half2float(hi));
            size_t dst = (size_t)(k >> 5) * CHUNK32_B + (size_t)n * 80 + (k & 31) * 2;
            *(__half*)(g_bt2 + dst)         = hi;
            *(__half*)(g_bt2 + dst + 10240) = lo;
        }
        return;
    }

    // enc role: M=64 x N=128 x K=512, 2-deep pipeline (bf16 split-3, unchanged)
    {
        int ebx = bx - 129;
        int b = ebx >> 5, tt = (ebx >> 2) & 7, nt = ebx & 3;
        int t0 = tt * 64;
        if (t0 >= es_arr[b]) return;
        int lane = tid & 31, wid = tid >> 5;
        int wm = wid & 1, wn = wid >> 1;     // 2m x 4n warps
        uint32_t sb = smem_u32(sm);

#define E_STAGE(c_) do {                                                            \
        int sl_ = (c_) & 1;                                                         \
        uint32_t rdst_ = sb + E_RAW + sl_ * 16896;                                  \
        _Pragma("unroll")                                                           \
        for (int i_ = 0; i_ < 4; i_++) {                                            \
            int idx_ = i_ * 256 + tid;                                              \
            int kk_ = idx_ >> 5, n4_ = idx_ & 31;                                   \
            CP_ASYNC16(rdst_ + kk_ * 528 + n4_ * 16,                                \
                &Wj1[(size_t)((c_) * 32 + kk_) * JOIN + nt * 128 + n4_ * 4]);       \
        }                                                                           \
        uint32_t edst_ = sb + E_ENC + sl_ * 8192;                                   \
        _Pragma("unroll")                                                           \
        for (int i_ = 0; i_ < 2; i_++) {                                            \
            int idx_ = i_ * 256 + tid;                                              \
            int row_ = idx_ >> 3, c4_ = idx_ & 7;                                   \
            CP_ASYNC16(edst_ + row_ * 128 + c4_ * 16,                               \
                &enc[(size_t)(b * T + t0 + row_) * ENC + (c_) * 32 + c4_ * 4]);     \
        }                                                                           \
    } while (0)

#define E_BUILD(c_) do {                                                            \
        int sl_ = (c_) & 1;                                                         \
        const float* s_raw_ = (const float*)(sm + E_RAW + sl_ * 16896);             \
        const float* s_enc_ = (const float*)(sm + E_ENC + sl_ * 8192);              \
        uint32_t ab_ = (uint32_t)E_A + sl_ * 10240;                                 \
        uint32_t bb_ = (uint32_t)E_B + sl_ * 20480;                                 \
        _Pragma("unroll")                                                           \
        for (int i_ = 0; i_ < 8; i_++) {       /* B: 2048 units */                  \
            int idx_ = i_ * 256 + tid;                                              \
            int n_ = idx_ & 127, kp_ = idx_ >> 7;                                   \
            float f0_ = s_raw_[(2 * kp_) * 132 + n_];                               \
            float f1_ = s_raw_[(2 * kp_ + 1) * 132 + n_];                           \
            __nv_bfloat162 hp_ = __floats2bfloat162_rn(f0_, f1_);                   \
            float2 hf_ = __bfloat1622float2(hp_);                                   \
            __nv_bfloat162 lp_ = __floats2bfloat162_rn(f0_ - hf_.x, f1_ - hf_.y);   \
            uint32_t off_ = bb_ + (uint32_t)n_ * 80 + kp_ * 4;                      \
            *(__nv_bfloat162*)(sm + off_) = hp_;                                    \
            *(__nv_bfloat162*)(sm + off_ + 10240) = lp_;                            \
        }                                                                           \
        _Pragma("unroll")                                                           \
        for (int i_ = 0; i_ < 4; i_++) {       /* A: 1024 units */                  \
            int idx_ = i_ * 256 + tid;                                              \
            int row_ = idx_ >> 4, kp_ = idx_ & 15;                                  \
            float2 e_ = *(const float2*)&s_enc_[row_ * 32 + 2 * kp_];               \
            __nv_bfloat162 hp_ = __floats2bfloat162_rn(e_.x, e_.y);                 \
            float2 hf_ = __bfloat1622float2(hp_);                                   \
            __nv_bfloat162 lp_ = __floats2bfloat162_rn(e_.x - hf_.x, e_.y - hf_.y); \
            uint32_t off_ = ab_ + (uint32_t)row_ * 80 + kp_ * 4;                    \
            *(__nv_bfloat162*)(sm + off_) = hp_;                                    \
            *(__nv_bfloat162*)(sm + off_ + 5120) = lp_;                             \
        }                                                                           \
    } while (0)

        float acc[2][4][4];
        #pragma unroll
        for (int i = 0; i < 2; i++)
            #pragma unroll
            for (int j = 0; j < 4; j++)
                #pragma unroll
                for (int q = 0; q < 4; q++) acc[i][j][q] = 0.f;

        uint32_t a_base = sb + E_A + (uint32_t)(wm * 32 + (lane & 15)) * 80
                        + ((lane >> 4) << 4);
        uint32_t b_base = sb + E_B + (uint32_t)(wn * 32 + (lane & 7) + ((lane >> 4) << 3)) * 80
                        + (((lane >> 3) & 1) << 4);

        E_STAGE(0); CP_COMMIT();
        CP_WAIT0();
        __syncthreads();
        E_BUILD(0);

        for (int c = 0; c < 16; c++) {
            __syncthreads();
            if (c + 1 < 16) { E_STAGE(c + 1); CP_COMMIT(); }
            {
                uint32_t ab = a_base + (c & 1) * 10240;
                uint32_t bb = b_base + (c & 1) * 20480;
                #pragma unroll
                for (int s = 0; s < 2; s++) {
                    uint32_t ah[2][4], al[2][4];
                    #pragma unroll
                    for (int mi = 0; mi < 2; mi++) {
                        ldsm4(ah[mi], ab + mi * 1280 + s * 32);
                        ldsm4(al[mi], ab + mi * 1280 + s * 32 + 5120);
                    }
                    #pragma unroll
                    for (int j2 = 0; j2 < 2; j2++) {
                        uint32_t bh[4], bl[4];
                        ldsm4(bh, bb + j2 * 1280 + s * 32);
                        ldsm4(bl, bb + j2 * 1280 + s * 32 + 10240);
                        #pragma unroll
                        for (int mi = 0; mi < 2; mi++)
                            #pragma unroll
                            for (int jj = 0; jj < 2; jj++) {
                                int nj = j2 * 2 + jj;
                                mma_bf16(acc[mi][nj], ah[mi], &bh[jj * 2]);
                                mma_bf16(acc[mi][nj], ah[mi], &bl[jj * 2]);
                                mma_bf16(acc[mi][nj], al[mi], &bh[jj * 2]);
                            }
                    }
                }
            }
            if (c + 1 < 16) {
                CP_WAIT0();
                __syncthreads();
                E_BUILD(c + 1);
            }
        }
#undef E_STAGE
#undef E_BUILD

        int gid = lane >> 2, tig = lane & 3;
        #pragma unroll
        for (int mi = 0; mi < 2; mi++)
            #pragma unroll
            for (int nj = 0; nj < 4; nj++) {
                int col = nt * 128 + wn * 32 + nj * 8 + tig * 2;
                #pragma unroll
                for (int hh = 0; hh < 2; hh++) {
                    int row = wm * 32 + mi * 16 + gid + hh * 8;
                    int t = t0 + row;
                    *(float2*)&g_ep[((size_t)(b * T + t)) * JOIN + col] =
                        make_float2(acc[mi][nj][hh * 2], acc[mi][nj][hh * 2 + 1]);
                }
            }
    }
}

// ======================================================================
// k_joint v5: fp16 A x fp16-split-2 B (2 MMA passes).
// M=128 (16t x 8u) x N=128, 256 threads, 2 blocks/SM.
// ONE barrier/chunk; warp-own ep staging + A-build; pp hoisted. grid=2304.
// ======================================================================
__global__ __launch_bounds__(256, 2)
void k_joint(const int* __restrict__ es_arr, const int* __restrict__ ts_arr,
             const float* __restrict__ bj2, float* __restrict__ out) {
    extern __shared__ char sm[];
    int bx = blockIdx.x;
    int b = bx / 288, rem = bx % 288;
    int t0 = (rem / 9) * 16, u0 = (rem % 9) * 8;
    int es = es_arr[b], ts = ts_arr[b];
    int tid = threadIdx.x;
    bool live = (t0 < es) && (u0 <= ts);

    if (!live) {
        float4 z = make_float4(0.f, 0.f, 0.f, 0.f);
        #pragma unroll
        for (int i = 0; i < 16; i++) {
            int f4 = i * 256 + tid;
            int row = f4 >> 5, c4 = f4 & 31;
            int t = t0 + (row >> 3), u = u0 + (row & 7);
            if (u < U1)
                *(float4*)(out + (((size_t)(b * T + t) * U1 + u) << 7) + c4 * 4) = z;
        }
        return;
    }

    int lane = tid & 31, wid = tid >> 5;
    int wm = wid & 3, wn = wid >> 2;
    uint32_t sb = smem_u32(sm);
    float* s_bias = (float*)(sm + J_BIAS);
    if (tid < 128) s_bias[tid] = bj2[tid];

    // ---- prologue: stage whole pp tile (8 rows x 512 = 1024 float4 units) ----
    #pragma unroll
    for (int i = 0; i < 4; i++) {
        int idx = i * 256 + tid;            // 0..1023
        int ui = idx >> 7, f4 = idx & 127;
        int uu = u0 + ui; if (uu > 64) uu = 64;
        CP_ASYNC16(sb + J_PP + ui * 2080 + f4 * 16,
                   &g_pp[((size_t)(b * U1 + uu)) * JOIN + f4 * 4]);
    }

#define STAGE_B(c_) do {                                                            \
        const char* bsrc_ = (const char*)g_bt2 + (size_t)(c_) * CHUNK32_B;          \
        uint32_t bdst_ = sb + J_B + ((c_) & 1) * CHUNK32_B;                         \
        _Pragma("unroll")                                                           \
        for (int i_ = 0; i_ < 5; i_++) {                                            \
            int idx_ = i_ * 256 + tid;                                              \
            CP_ASYNC16(bdst_ + idx_ * 16, bsrc_ + idx_ * 16);                       \
        }                                                                           \
    } while (0)

    // per-warp ep staging: warp wid stages ti rows {2*wid, 2*wid+1}
#define STAGE_EP(c_) do {                                                           \
        if (lane < 16) {                                                            \
            int tl_ = lane >> 3, c4_ = lane & 7;                                    \
            int ti_ = wid * 2 + tl_;                                                \
            CP_ASYNC16(sb + J_EP + ((c_) & 1) * 2048 + ti_ * 128 + c4_ * 16,        \
                &g_ep[((size_t)(b * T + t0 + ti_)) * JOIN + (c_) * 32 + c4_ * 4]);  \
        }                                                                           \
    } while (0)

    // per-warp A build (fp16 hi only): warp wid builds rows 16*wid .. 16*wid+15
#define BUILD_A(c_) do {                                                            \
        uint32_t ab_ = (uint32_t)J_A + ((c_) & 1) * A_BUF_B;                        \
        const float* s_ep_ = (const float*)(sm + J_EP + ((c_) & 1) * 2048);         \
        const float* s_pp_ = (const float*)(sm + J_PP);                             \
        _Pragma("unroll")                                                           \
        for (int i_ = 0; i_ < 8; i_++) {                                            \
            int p_ = i_ * 32 + lane;                                                \
            int rl_ = p_ >> 4, kp_ = p_ & 15;                                       \
            int row_ = wid * 16 + rl_;                                              \
            int ti_ = row_ >> 3, ui_ = row_ & 7;                                    \
            float2 e_ = *(const float2*)&s_ep_[ti_ * 32 + 2 * kp_];                 \
            float2 q_ = *(const float2*)&s_pp_[ui_ * 520 + (c_) * 32 + 2 * kp_];    \
            float h0_ = fmaxf(e_.x + q_.x, 0.f), h1_ = fmaxf(e_.y + q_.y, 0.f);     \
            __half2 hp_ = __floats2half2_rn(h0_, h1_);                              \
            uint32_t off_ = ab_ + (uint32_t)row_ * 80 + kp_ * 4;                    \
            *(__half2*)(sm + off_) = hp_;                                           \
        }                                                                           \
    } while (0)

    float acc[2][8][4];
    #pragma unroll
    for (int i = 0; i < 2; i++)
        #pragma unroll
        for (int j = 0; j < 8; j++)
            #pragma unroll
            for (int q = 0; q < 4; q++) acc[i][j][q] = 0.f;

    uint32_t a_base = sb + J_A + (uint32_t)(wm * 32 + (lane & 15)) * 80 + ((lane >> 4) << 4);
    uint32_t b_base = sb + J_B + (uint32_t)(wn * 64 + (lane & 7) + ((lane >> 4) << 3)) * 80
                    + (((lane >> 3) & 1) << 4);

    // prologue: stage chunk 0 (pp already queued in the same group)
    STAGE_B(0);
    STAGE_EP(0);
    CP_COMMIT();
    CP_WAIT0();
    __syncthreads();          // pp + B(0) + ep(0) visible block-wide
    BUILD_A(0);

    for (int c = 0; c < 16; c++) {
        __syncthreads();      // A(c) built by all warps; B(c) staged & visible
        if (c + 1 < 16) { STAGE_B(c + 1); STAGE_EP(c + 1); CP_COMMIT(); }
        // ---- MMA(c): 2 passes (A*Bhi + A*Blo) ----
        {
            uint32_t ab = a_base + (c & 1) * A_BUF_B;
            uint32_t bb = b_base + (c & 1) * CHUNK32_B;
            #pragma unroll
            for (int s = 0; s < 2; s++) {
                uint32_t ah[2][4];
                #pragma unroll
                for (int mi = 0; mi < 2; mi++)
                    ldsm4(ah[mi], ab + mi * 1280 + s * 32);
                #pragma unroll
                for (int j2 = 0; j2 < 4; j2++) {
                    uint32_t bh[4], bl[4];
                    ldsm4(bh, bb + j2 * 1280 + s * 32);
                    ldsm4(bl, bb + j2 * 1280 + s * 32 + 10240);
                    #pragma unroll
                    for (int mi = 0; mi < 2; mi++)
                        #pragma unroll
                        for (int jj = 0; jj < 2; jj++) {
                            int nj = j2 * 2 + jj;
                            mma_f16(acc[mi][nj], ah[mi], &bh[jj * 2]);
                            mma_f16(acc[mi][nj], ah[mi], &bl[jj * 2]);
                        }
                }
            }
        }
        // ---- build A(c+1): warp-private ----
        if (c + 1 < 16) {
            CP_WAIT0();       // own B+ep copies done
            __syncwarp();     // ep staged by lanes<16 visible warp-wide
            BUILD_A(c + 1);
        }
    }
#undef STAGE_B
#undef STAGE_EP
#undef BUILD_A

    // epilogue: bias + mask + store
    int gid = lane >> 2, tig = lane & 3;
    #pragma unroll
    for (int mi = 0; mi < 2; mi++)
        #pragma unroll
        for (int nj = 0; nj < 8; nj++) {
            int col = wn * 64 + nj * 8 + tig * 2;
            float b0f = s_bias[col], b1f = s_bias[col + 1];
            #pragma unroll
            for (int hh = 0; hh < 2; hh++) {
                int row = wm * 32 + mi * 16 + gid + hh * 8;
                int t = t0 + (row >> 3), u = u0 + (row & 7);
                if (u >= U1) continue;
                bool valid = (t < es) && (u <= ts);
                float v0 = valid ? acc[mi][nj][hh * 2]     + b0f : 0.f;
                float v1 = valid ? acc[mi][nj][hh * 2 + 1] + b1f : 0.f;
                *(float2*)(out + (((size_t)(b * T + t) * U1 + u) << 7) + col) =
                    make_float2(v0, v1);
            }
        }
}

extern "C" void kernel_launch(void* const* d_in, const int* in_sizes, int n_in,
                              void* d_out, int out_size) {
    const float* enc  = (const float*)d_in[0];
    const int*   es   = (const int*)  d_in[1];
    const void*  tgt  =               d_in[2];   // int64 or int32, auto-detected
    const int*   ts   = (const int*)  d_in[3];
    const float* emb  = (const float*)d_in[4];
    const float* W1   = (const float*)d_in[5];
    const float* b1   = (const float*)d_in[6];
    const float* W2   = (const float*)d_in[7];
    const float* b2   = (const float*)d_in[8];
    const float* Wj1  = (const float*)d_in[9];
    const float* bj1  = (const float*)d_in[10];
    const float* Wj2  = (const float*)d_in[11];
    const float* bj2  = (const float*)d_in[12];
    float* out = (float*)d_out;

    static bool attr_done = false;
    if (!attr_done) {
        cudaFuncSetAttribute(k_all,   cudaFuncAttributeMaxDynamicSharedMemorySize, SMEM_ALL3);
        cudaFuncSetAttribute(k_joint, cudaFuncAttributeMaxDynamicSharedMemorySize, SMEM_J5);
        attr_done = true;
    }

    k_all  <<<385, 256, SMEM_ALL3>>>(enc, es, tgt, emb, W1, b1, W2, b2, Wj1, bj1, Wj2);
    k_joint<<<2304, 256, SMEM_J5>>>(es, ts, bj2, out);
}